// round 5
// baseline (speedup 1.0000x reference)
#include <cuda_runtime.h>
#include <cuda_bf16.h>
#include <math.h>

// Problem constants (fixed by the dataset)
#define N_NODES  100000
#define N_EDGES  1600000
#define N_FEAT   512
#define HIDDEN   128
#define N_CLASS  40

// ---------------- scratch (device globals; no cudaMalloc allowed) ------------
__device__ __align__(16) float g_deg [N_NODES];
__device__ __align__(16) float g_dinv[N_NODES];
__device__ __align__(16) int   g_src [N_EDGES];
__device__ __align__(16) int   g_dst [N_EDGES];
__device__ __align__(16) float g_w   [N_EDGES];
__device__ __align__(16) float g_h   [(size_t)N_NODES * HIDDEN];   // x @ W1
__device__ __align__(16) float g_a1  [(size_t)N_NODES * HIDDEN];   // aggregated layer1
__device__ __align__(16) float g_h2  [(size_t)N_NODES * N_CLASS];  // relu(a1+b1) @ W2
__device__ __align__(16) float g_a2  [(size_t)N_NODES * N_CLASS];  // aggregated logits (pre-bias)
__device__ int g_is64;

// ---------------- dtype detection -------------------------------------------
// edge_index may be int64 (reference asks for it) or int32 (JAX x64 disabled).
// If int64: every odd 32-bit word (high half) of the first 8 entries is 0.
__global__ void k_detect(const unsigned* __restrict__ ei_u32) {
    int all_zero = 1;
    #pragma unroll
    for (int i = 0; i < 8; i++) {
        if (ei_u32[2 * i + 1] != 0u) all_zero = 0;
    }
    g_is64 = all_zero;
}

__global__ void k_init_deg() {
    int i = blockIdx.x * blockDim.x + threadIdx.x;
    if (i < N_NODES) g_deg[i] = 1.0f;   // self-loop contributes 1
}

// unpack edges to int32 + accumulate degree on dst
__global__ void k_prep_edges(const void* __restrict__ ei_raw) {
    int e = blockIdx.x * blockDim.x + threadIdx.x;
    if (e >= N_EDGES) return;
    int s, d;
    if (g_is64) {
        const long long* ei = (const long long*)ei_raw;
        s = (int)ei[e];
        d = (int)ei[N_EDGES + e];
    } else {
        const int* ei = (const int*)ei_raw;
        s = ei[e];
        d = ei[N_EDGES + e];
    }
    g_src[e] = s;
    g_dst[e] = d;
    atomicAdd(&g_deg[d], 1.0f);
}

__global__ void k_dinv() {
    int i = blockIdx.x * blockDim.x + threadIdx.x;
    if (i < N_NODES) g_dinv[i] = rsqrtf(g_deg[i]);  // deg >= 1 always
}

__global__ void k_edge_w() {
    int e = blockIdx.x * blockDim.x + threadIdx.x;
    if (e >= N_EDGES) return;
    g_w[e] = g_dinv[g_src[e]] * g_dinv[g_dst[e]];
}

// ---------------- GEMM1: g_h = x @ W1   [100000,512]@[512,128] ---------------
#define BM 128
#define BN 128
#define BK 32
#define AS_PAD 132

__global__ __launch_bounds__(256) void k_gemm1(const float* __restrict__ X,
                                               const float* __restrict__ W) {
    __shared__ float As[BK][AS_PAD];   // transposed: As[k][m]
    __shared__ float Bs[BK][BN];

    int tid = threadIdx.x;
    int tx = tid & 15;           // 16 cols of threads
    int ty = tid >> 4;           // 16 rows of threads
    int rowBase = blockIdx.x * BM;

    float acc[8][8];
    #pragma unroll
    for (int i = 0; i < 8; i++)
        #pragma unroll
        for (int j = 0; j < 8; j++) acc[i][j] = 0.0f;

    for (int k0 = 0; k0 < N_FEAT; k0 += BK) {
        // A tile: 128 rows x 32 k  -> 1024 float4 slots, 4 per thread
        #pragma unroll
        for (int i = 0; i < 4; i++) {
            int slot = tid + i * 256;
            int m  = slot >> 3;       // row in tile
            int kq = slot & 7;        // float4 index in k
            float4 v = make_float4(0.f, 0.f, 0.f, 0.f);
            int gr = rowBase + m;
            if (gr < N_NODES)
                v = *(const float4*)&X[(size_t)gr * N_FEAT + k0 + kq * 4];
            As[kq * 4 + 0][m] = v.x;
            As[kq * 4 + 1][m] = v.y;
            As[kq * 4 + 2][m] = v.z;
            As[kq * 4 + 3][m] = v.w;
        }
        // B tile: 32 k x 128 n
        #pragma unroll
        for (int i = 0; i < 4; i++) {
            int slot = tid + i * 256;
            int kk = slot >> 5;
            int nq = slot & 31;
            float4 v = *(const float4*)&W[(size_t)(k0 + kk) * HIDDEN + nq * 4];
            *(float4*)&Bs[kk][nq * 4] = v;
        }
        __syncthreads();

        #pragma unroll
        for (int kk = 0; kk < BK; kk++) {
            float4 a0 = *(const float4*)&As[kk][ty * 8];
            float4 a1 = *(const float4*)&As[kk][ty * 8 + 4];
            float4 b0 = *(const float4*)&Bs[kk][tx * 8];
            float4 b1 = *(const float4*)&Bs[kk][tx * 8 + 4];
            float a[8] = {a0.x, a0.y, a0.z, a0.w, a1.x, a1.y, a1.z, a1.w};
            float b[8] = {b0.x, b0.y, b0.z, b0.w, b1.x, b1.y, b1.z, b1.w};
            #pragma unroll
            for (int i = 0; i < 8; i++)
                #pragma unroll
                for (int j = 0; j < 8; j++)
                    acc[i][j] = fmaf(a[i], b[j], acc[i][j]);
        }
        __syncthreads();
    }

    #pragma unroll
    for (int i = 0; i < 8; i++) {
        int gr = rowBase + ty * 8 + i;
        if (gr < N_NODES) {
            #pragma unroll
            for (int j = 0; j < 8; j += 4) {
                float4 v = make_float4(acc[i][j], acc[i][j + 1], acc[i][j + 2], acc[i][j + 3]);
                *(float4*)&g_h[(size_t)gr * HIDDEN + tx * 8 + j] = v;
            }
        }
    }
}

// ---------------- aggregation layer 1 ----------------------------------------
// self-loop init: a1[i, :] = h[i, :] * dinv[i]^2
__global__ void k_self1() {
    int i = blockIdx.x * blockDim.x + threadIdx.x;   // over N*H/4 float4s
    if (i >= N_NODES * HIDDEN / 4) return;
    int node = i / (HIDDEN / 4);
    float di = g_dinv[node];
    float w = di * di;
    float4 v = *(const float4*)&g_h[(size_t)i * 4];
    v.x *= w; v.y *= w; v.z *= w; v.w *= w;
    *(float4*)&g_a1[(size_t)i * 4] = v;
}

// scatter: a1[dst, :] += h[src, :] * w    (32 lanes per edge, float4 each)
__global__ void k_agg1() {
    int t = blockIdx.x * blockDim.x + threadIdx.x;
    int e = t >> 5;
    if (e >= N_EDGES) return;
    int lane = t & 31;
    int s = g_src[e];
    int d = g_dst[e];
    float w = g_w[e];
    float4 v = *(const float4*)&g_h[(size_t)s * HIDDEN + lane * 4];
    v.x *= w; v.y *= w; v.z *= w; v.w *= w;
    float* p = &g_a1[(size_t)d * HIDDEN + lane * 4];
    asm volatile("red.global.add.v4.f32 [%0], {%1,%2,%3,%4};"
                 :: "l"(p), "f"(v.x), "f"(v.y), "f"(v.z), "f"(v.w) : "memory");
}

// ---------------- GEMM2: g_h2 = relu(a1 + b1) @ W2  [N,128]@[128,40] ----------
#define G2_ROWS 32
__global__ __launch_bounds__(256) void k_gemm2(const float* __restrict__ W2,
                                               const float* __restrict__ b1) {
    __shared__ float sW[HIDDEN * N_CLASS];       // 20 KB
    __shared__ float sH[G2_ROWS][HIDDEN + 4];    // padded

    int tid = threadIdx.x;
    for (int i = tid; i < HIDDEN * N_CLASS; i += 256) sW[i] = W2[i];

    int rowBase = blockIdx.x * G2_ROWS;
    for (int i = tid; i < G2_ROWS * HIDDEN; i += 256) {
        int r = i >> 7;        // /128
        int k = i & 127;
        int gr = rowBase + r;
        float v = 0.0f;
        if (gr < N_NODES) v = g_a1[(size_t)gr * HIDDEN + k] + b1[k];
        sH[r][k] = fmaxf(v, 0.0f);
    }
    __syncthreads();

    for (int o = tid; o < G2_ROWS * N_CLASS; o += 256) {
        int r = o / N_CLASS;
        int c = o % N_CLASS;
        float acc = 0.0f;
        #pragma unroll 8
        for (int k = 0; k < HIDDEN; k++)
            acc = fmaf(sH[r][k], sW[k * N_CLASS + c], acc);
        int gr = rowBase + r;
        if (gr < N_NODES) g_h2[(size_t)gr * N_CLASS + c] = acc;
    }
}

// ---------------- aggregation layer 2 ----------------------------------------
__global__ void k_self2() {
    int i = blockIdx.x * blockDim.x + threadIdx.x;   // over N*C/4 float4s
    if (i >= N_NODES * N_CLASS / 4) return;
    int node = i / (N_CLASS / 4);
    float di = g_dinv[node];
    float w = di * di;
    float4 v = *(const float4*)&g_h2[(size_t)i * 4];
    v.x *= w; v.y *= w; v.z *= w; v.w *= w;
    *(float4*)&g_a2[(size_t)i * 4] = v;
}

// 10 float4 per edge (40 floats)
__global__ void k_agg2() {
    int t = blockIdx.x * blockDim.x + threadIdx.x;
    int e = t / 10;
    if (e >= N_EDGES) return;
    int q = t % 10;
    int s = g_src[e];
    int d = g_dst[e];
    float w = g_w[e];
    float4 v = *(const float4*)&g_h2[(size_t)s * N_CLASS + q * 4];
    v.x *= w; v.y *= w; v.z *= w; v.w *= w;
    float* p = &g_a2[(size_t)d * N_CLASS + q * 4];
    asm volatile("red.global.add.v4.f32 [%0], {%1,%2,%3,%4};"
                 :: "l"(p), "f"(v.x), "f"(v.y), "f"(v.z), "f"(v.w) : "memory");
}

// ---------------- log_softmax(a2 + b2) -> out --------------------------------
__global__ void k_lsm(const float* __restrict__ b2, float* __restrict__ out) {
    int r = blockIdx.x * 4 + (threadIdx.x >> 5);
    if (r >= N_NODES) return;
    int lane = threadIdx.x & 31;

    float x0 = g_a2[(size_t)r * N_CLASS + lane] + b2[lane];
    float x1 = -1e30f;
    if (lane < 8) x1 = g_a2[(size_t)r * N_CLASS + 32 + lane] + b2[32 + lane];

    float m = fmaxf(x0, x1);
    #pragma unroll
    for (int o = 16; o > 0; o >>= 1) m = fmaxf(m, __shfl_xor_sync(0xFFFFFFFFu, m, o));

    float s = expf(x0 - m) + ((lane < 8) ? expf(x1 - m) : 0.0f);
    #pragma unroll
    for (int o = 16; o > 0; o >>= 1) s += __shfl_xor_sync(0xFFFFFFFFu, s, o);

    float ls = m + logf(s);
    out[(size_t)r * N_CLASS + lane] = x0 - ls;
    if (lane < 8) out[(size_t)r * N_CLASS + 32 + lane] = x1 - ls;
}

// ---------------- launcher ----------------------------------------------------
extern "C" void kernel_launch(void* const* d_in, const int* in_sizes, int n_in,
                              void* d_out, int out_size) {
    const float* x  = (const float*)d_in[0];
    const void*  ei = d_in[1];
    const float* W1 = (const float*)d_in[2];
    const float* b1 = (const float*)d_in[3];
    const float* W2 = (const float*)d_in[4];
    const float* b2 = (const float*)d_in[5];
    float* out = (float*)d_out;

    k_detect<<<1, 1>>>((const unsigned*)ei);
    k_init_deg<<<(N_NODES + 255) / 256, 256>>>();
    k_prep_edges<<<(N_EDGES + 255) / 256, 256>>>(ei);
    k_dinv<<<(N_NODES + 255) / 256, 256>>>();
    k_edge_w<<<(N_EDGES + 255) / 256, 256>>>();

    k_gemm1<<<(N_NODES + BM - 1) / BM, 256>>>(x, W1);
    k_self1<<<(N_NODES * HIDDEN / 4 + 255) / 256, 256>>>();
    k_agg1<<<(N_EDGES * 32 + 255) / 256, 256>>>();

    k_gemm2<<<(N_NODES + G2_ROWS - 1) / G2_ROWS, 256>>>(W2, b1);
    k_self2<<<(N_NODES * N_CLASS / 4 + 255) / 256, 256>>>();
    k_agg2<<<(N_EDGES * 10 + 255) / 256, 256>>>();

    k_lsm<<<(N_NODES + 3) / 4, 128>>>(b2, out);
}

// round 6
// speedup vs baseline: 1.3095x; 1.3095x over previous
#include <cuda_runtime.h>
#include <cuda_bf16.h>
#include <math.h>

// Problem constants (fixed by the dataset)
#define N_NODES  100000
#define N_EDGES  1600000
#define N_FEAT   512
#define HIDDEN   128
#define N_CLASS  40

// ---------------- scratch (device globals; no cudaMalloc allowed) ------------
__device__ __align__(16) float g_deg [N_NODES];
__device__ __align__(16) float g_dinv[N_NODES];
__device__ __align__(16) int   g_src [N_EDGES];
__device__ __align__(16) int   g_dst [N_EDGES];
__device__ __align__(16) float g_w   [N_EDGES];
__device__ __align__(16) float g_h   [(size_t)N_NODES * HIDDEN];   // x @ W1
__device__ __align__(16) float g_a1  [(size_t)N_NODES * HIDDEN];   // aggregated layer1
__device__ __align__(16) float g_h2  [(size_t)N_NODES * N_CLASS];  // relu(a1+b1) @ W2
__device__ __align__(16) float g_a2  [(size_t)N_NODES * N_CLASS];  // aggregated logits (pre-bias)
__device__ int g_is64;

// ---------------- dtype detection -------------------------------------------
__global__ void k_detect(const unsigned* __restrict__ ei_u32) {
    int all_zero = 1;
    #pragma unroll
    for (int i = 0; i < 8; i++) {
        if (ei_u32[2 * i + 1] != 0u) all_zero = 0;
    }
    g_is64 = all_zero;
}

__global__ void k_init_deg() {
    int i = blockIdx.x * blockDim.x + threadIdx.x;
    if (i < N_NODES) g_deg[i] = 1.0f;   // self-loop contributes 1
}

__global__ void k_prep_edges(const void* __restrict__ ei_raw) {
    int e = blockIdx.x * blockDim.x + threadIdx.x;
    if (e >= N_EDGES) return;
    int s, d;
    if (g_is64) {
        const long long* ei = (const long long*)ei_raw;
        s = (int)ei[e];
        d = (int)ei[N_EDGES + e];
    } else {
        const int* ei = (const int*)ei_raw;
        s = ei[e];
        d = ei[N_EDGES + e];
    }
    g_src[e] = s;
    g_dst[e] = d;
    atomicAdd(&g_deg[d], 1.0f);
}

__global__ void k_dinv() {
    int i = blockIdx.x * blockDim.x + threadIdx.x;
    if (i < N_NODES) g_dinv[i] = rsqrtf(g_deg[i]);  // deg >= 1 always
}

__global__ void k_edge_w() {
    int e = blockIdx.x * blockDim.x + threadIdx.x;
    if (e >= N_EDGES) return;
    g_w[e] = g_dinv[g_src[e]] * g_dinv[g_dst[e]];
}

// ---------------- GEMM1 (tensor core tf32): g_h = x @ W1 ---------------------
// Block tile 128x128, K-step 32. 8 warps in 2(M) x 4(N); warp tile 64x32.
// mma.sync.aligned.m16n8k8 tf32, fp32 accumulate.
#define BM 128
#define BK 32
#define A_PAD 36     // 128 rows x 36 cols (uint32), conflict-free frag reads
#define B_PAD 132    // 32 rows  x 132 cols

__device__ __forceinline__ unsigned f2tf(float f) {
    unsigned r;
    asm("cvt.rna.tf32.f32 %0, %1;" : "=r"(r) : "f"(f));
    return r;
}

__device__ __forceinline__ void mma_tf32(float c[4], const unsigned a[4], const unsigned b[2]) {
    asm volatile(
        "mma.sync.aligned.m16n8k8.row.col.f32.tf32.tf32.f32 "
        "{%0,%1,%2,%3}, {%4,%5,%6,%7}, {%8,%9}, {%0,%1,%2,%3};"
        : "+f"(c[0]), "+f"(c[1]), "+f"(c[2]), "+f"(c[3])
        : "r"(a[0]), "r"(a[1]), "r"(a[2]), "r"(a[3]), "r"(b[0]), "r"(b[1]));
}

__global__ __launch_bounds__(256, 2) void k_gemm1_tc(const float* __restrict__ X,
                                                     const float* __restrict__ W) {
    __shared__ unsigned As[BM][A_PAD];   // As[m][k]
    __shared__ unsigned Bs[BK][B_PAD];   // Bs[k][n]

    const int tid = threadIdx.x;
    const int wid = tid >> 5;
    const int lane = tid & 31;
    const int g  = lane >> 2;   // groupID (0..7)
    const int tg = lane & 3;    // thread-in-group (0..3)
    const int wm = wid >> 2;    // 0..1  (M)
    const int wn = wid & 3;     // 0..3  (N)
    const int mBase = wm * 64;
    const int nBase = wn * 32;
    const int rowBase = blockIdx.x * BM;

    float c[4][4][4];
    #pragma unroll
    for (int mi = 0; mi < 4; mi++)
        #pragma unroll
        for (int ni = 0; ni < 4; ni++)
            #pragma unroll
            for (int r = 0; r < 4; r++) c[mi][ni][r] = 0.0f;

    for (int k0 = 0; k0 < N_FEAT; k0 += BK) {
        // ---- A tile: 128 rows x 32 k -> 1024 float4 slots, 4 per thread ----
        #pragma unroll
        for (int i = 0; i < 4; i++) {
            int slot = tid + i * 256;
            int m  = slot >> 3;
            int kq = slot & 7;
            float4 v = make_float4(0.f, 0.f, 0.f, 0.f);
            int gr = rowBase + m;
            if (gr < N_NODES)
                v = *(const float4*)&X[(size_t)gr * N_FEAT + k0 + kq * 4];
            unsigned* p = &As[m][kq * 4];
            p[0] = f2tf(v.x); p[1] = f2tf(v.y); p[2] = f2tf(v.z); p[3] = f2tf(v.w);
        }
        // ---- B tile: 32 k x 128 n ----
        #pragma unroll
        for (int i = 0; i < 4; i++) {
            int slot = tid + i * 256;
            int kk = slot >> 5;
            int nq = slot & 31;
            float4 v = *(const float4*)&W[(size_t)(k0 + kk) * HIDDEN + nq * 4];
            unsigned* p = &Bs[kk][nq * 4];
            p[0] = f2tf(v.x); p[1] = f2tf(v.y); p[2] = f2tf(v.z); p[3] = f2tf(v.w);
        }
        __syncthreads();

        #pragma unroll
        for (int ks = 0; ks < 4; ks++) {
            const int kb = ks * 8;
            unsigned a[4][4];
            #pragma unroll
            for (int mi = 0; mi < 4; mi++) {
                int r0 = mBase + mi * 16 + g;
                a[mi][0] = As[r0    ][kb + tg];
                a[mi][1] = As[r0 + 8][kb + tg];
                a[mi][2] = As[r0    ][kb + tg + 4];
                a[mi][3] = As[r0 + 8][kb + tg + 4];
            }
            unsigned b[4][2];
            #pragma unroll
            for (int ni = 0; ni < 4; ni++) {
                int col = nBase + ni * 8 + g;
                b[ni][0] = Bs[kb + tg    ][col];
                b[ni][1] = Bs[kb + tg + 4][col];
            }
            #pragma unroll
            for (int mi = 0; mi < 4; mi++)
                #pragma unroll
                for (int ni = 0; ni < 4; ni++)
                    mma_tf32(c[mi][ni], a[mi], b[ni]);
        }
        __syncthreads();
    }

    // ---- epilogue: c0,c1 -> (row, 2tg), (row, 2tg+1); c2,c3 -> row+8 ----
    #pragma unroll
    for (int mi = 0; mi < 4; mi++) {
        int r0 = rowBase + mBase + mi * 16 + g;
        #pragma unroll
        for (int ni = 0; ni < 4; ni++) {
            int col = nBase + ni * 8 + tg * 2;
            if (r0 < N_NODES)
                *(float2*)&g_h[(size_t)r0 * HIDDEN + col] = make_float2(c[mi][ni][0], c[mi][ni][1]);
            if (r0 + 8 < N_NODES)
                *(float2*)&g_h[(size_t)(r0 + 8) * HIDDEN + col] = make_float2(c[mi][ni][2], c[mi][ni][3]);
        }
    }
}

// ---------------- aggregation layer 1 ----------------------------------------
__global__ void k_self1() {
    int i = blockIdx.x * blockDim.x + threadIdx.x;   // over N*H/4 float4s
    if (i >= N_NODES * HIDDEN / 4) return;
    int node = i / (HIDDEN / 4);
    float di = g_dinv[node];
    float w = di * di;
    float4 v = *(const float4*)&g_h[(size_t)i * 4];
    v.x *= w; v.y *= w; v.z *= w; v.w *= w;
    *(float4*)&g_a1[(size_t)i * 4] = v;
}

__global__ void k_agg1() {
    int t = blockIdx.x * blockDim.x + threadIdx.x;
    int e = t >> 5;
    if (e >= N_EDGES) return;
    int lane = t & 31;
    int s = g_src[e];
    int d = g_dst[e];
    float w = g_w[e];
    float4 v = *(const float4*)&g_h[(size_t)s * HIDDEN + lane * 4];
    v.x *= w; v.y *= w; v.z *= w; v.w *= w;
    float* p = &g_a1[(size_t)d * HIDDEN + lane * 4];
    asm volatile("red.global.add.v4.f32 [%0], {%1,%2,%3,%4};"
                 :: "l"(p), "f"(v.x), "f"(v.y), "f"(v.z), "f"(v.w) : "memory");
}

// ---------------- GEMM2: g_h2 = relu(a1 + b1) @ W2  [N,128]@[128,40] ----------
#define G2_ROWS 32
__global__ __launch_bounds__(256) void k_gemm2(const float* __restrict__ W2,
                                               const float* __restrict__ b1) {
    __shared__ float sW[HIDDEN * N_CLASS];       // 20 KB
    __shared__ float sH[G2_ROWS][HIDDEN + 4];    // padded

    int tid = threadIdx.x;
    for (int i = tid; i < HIDDEN * N_CLASS; i += 256) sW[i] = W2[i];

    int rowBase = blockIdx.x * G2_ROWS;
    for (int i = tid; i < G2_ROWS * HIDDEN; i += 256) {
        int r = i >> 7;        // /128
        int k = i & 127;
        int gr = rowBase + r;
        float v = 0.0f;
        if (gr < N_NODES) v = g_a1[(size_t)gr * HIDDEN + k] + b1[k];
        sH[r][k] = fmaxf(v, 0.0f);
    }
    __syncthreads();

    for (int o = tid; o < G2_ROWS * N_CLASS; o += 256) {
        int r = o / N_CLASS;
        int c = o % N_CLASS;
        float acc = 0.0f;
        #pragma unroll 8
        for (int k = 0; k < HIDDEN; k++)
            acc = fmaf(sH[r][k], sW[k * N_CLASS + c], acc);
        int gr = rowBase + r;
        if (gr < N_NODES) g_h2[(size_t)gr * N_CLASS + c] = acc;
    }
}

// ---------------- aggregation layer 2 ----------------------------------------
__global__ void k_self2() {
    int i = blockIdx.x * blockDim.x + threadIdx.x;   // over N*C/4 float4s
    if (i >= N_NODES * N_CLASS / 4) return;
    int node = i / (N_CLASS / 4);
    float di = g_dinv[node];
    float w = di * di;
    float4 v = *(const float4*)&g_h2[(size_t)i * 4];
    v.x *= w; v.y *= w; v.z *= w; v.w *= w;
    *(float4*)&g_a2[(size_t)i * 4] = v;
}

__global__ void k_agg2() {
    int t = blockIdx.x * blockDim.x + threadIdx.x;
    int e = t / 10;
    if (e >= N_EDGES) return;
    int q = t % 10;
    int s = g_src[e];
    int d = g_dst[e];
    float w = g_w[e];
    float4 v = *(const float4*)&g_h2[(size_t)s * N_CLASS + q * 4];
    v.x *= w; v.y *= w; v.z *= w; v.w *= w;
    float* p = &g_a2[(size_t)d * N_CLASS + q * 4];
    asm volatile("red.global.add.v4.f32 [%0], {%1,%2,%3,%4};"
                 :: "l"(p), "f"(v.x), "f"(v.y), "f"(v.z), "f"(v.w) : "memory");
}

// ---------------- log_softmax(a2 + b2) -> out --------------------------------
__global__ void k_lsm(const float* __restrict__ b2, float* __restrict__ out) {
    int r = blockIdx.x * 4 + (threadIdx.x >> 5);
    if (r >= N_NODES) return;
    int lane = threadIdx.x & 31;

    float x0 = g_a2[(size_t)r * N_CLASS + lane] + b2[lane];
    float x1 = -1e30f;
    if (lane < 8) x1 = g_a2[(size_t)r * N_CLASS + 32 + lane] + b2[32 + lane];

    float m = fmaxf(x0, x1);
    #pragma unroll
    for (int o = 16; o > 0; o >>= 1) m = fmaxf(m, __shfl_xor_sync(0xFFFFFFFFu, m, o));

    float s = expf(x0 - m) + ((lane < 8) ? expf(x1 - m) : 0.0f);
    #pragma unroll
    for (int o = 16; o > 0; o >>= 1) s += __shfl_xor_sync(0xFFFFFFFFu, s, o);

    float ls = m + logf(s);
    out[(size_t)r * N_CLASS + lane] = x0 - ls;
    if (lane < 8) out[(size_t)r * N_CLASS + 32 + lane] = x1 - ls;
}

// ---------------- launcher ----------------------------------------------------
extern "C" void kernel_launch(void* const* d_in, const int* in_sizes, int n_in,
                              void* d_out, int out_size) {
    const float* x  = (const float*)d_in[0];
    const void*  ei = d_in[1];
    const float* W1 = (const float*)d_in[2];
    const float* b1 = (const float*)d_in[3];
    const float* W2 = (const float*)d_in[4];
    const float* b2 = (const float*)d_in[5];
    float* out = (float*)d_out;

    k_detect<<<1, 1>>>((const unsigned*)ei);
    k_init_deg<<<(N_NODES + 255) / 256, 256>>>();
    k_prep_edges<<<(N_EDGES + 255) / 256, 256>>>(ei);
    k_dinv<<<(N_NODES + 255) / 256, 256>>>();
    k_edge_w<<<(N_EDGES + 255) / 256, 256>>>();

    k_gemm1_tc<<<(N_NODES + BM - 1) / BM, 256>>>(x, W1);
    k_self1<<<(N_NODES * HIDDEN / 4 + 255) / 256, 256>>>();
    k_agg1<<<(N_EDGES * 32 + 255) / 256, 256>>>();

    k_gemm2<<<(N_NODES + G2_ROWS - 1) / G2_ROWS, 256>>>(W2, b1);
    k_self2<<<(N_NODES * N_CLASS / 4 + 255) / 256, 256>>>();
    k_agg2<<<(N_EDGES * 10 + 255) / 256, 256>>>();

    k_lsm<<<(N_NODES + 3) / 4, 128>>>(b2, out);
}

// round 7
// speedup vs baseline: 1.8968x; 1.4485x over previous
#include <cuda_runtime.h>
#include <cuda_bf16.h>
#include <math.h>

// Problem constants (fixed by the dataset)
#define N_NODES  100000
#define N_EDGES  1600000
#define N_FEAT   512
#define HIDDEN   128
#define N_CLASS  40

#define SCAN_BLK   1024                      // elems per scan block
#define SCAN_NBLK  ((N_NODES + SCAN_BLK - 1) / SCAN_BLK)   // 98

// ---------------- scratch (device globals; no cudaMalloc allowed) ------------
__device__ __align__(16) int   g_cnt   [N_NODES];      // in-degree (excl self)
__device__ __align__(16) float g_dinv  [N_NODES];
__device__ __align__(16) int   g_rowptr[N_NODES + 1];
__device__ __align__(16) int   g_pos   [N_NODES];      // scatter cursor
__device__ __align__(16) int   g_bsum  [SCAN_NBLK];
__device__ __align__(16) int   g_boff  [SCAN_NBLK];
__device__ __align__(16) int   g_csrc  [N_EDGES];      // src sorted by dst
__device__ __align__(16) float g_cw    [N_EDGES];      // edge weight sorted by dst
__device__ __align__(16) float g_h   [(size_t)N_NODES * HIDDEN];   // x @ W1
__device__ __align__(16) float g_a1  [(size_t)N_NODES * HIDDEN];   // aggregated layer1
__device__ __align__(16) float g_h2  [(size_t)N_NODES * N_CLASS];  // relu(a1+b1) @ W2
__device__ __align__(16) float g_a2  [(size_t)N_NODES * N_CLASS];  // aggregated logits
__device__ int g_is64;

// ---------------- dtype detection -------------------------------------------
__global__ void k_detect(const unsigned* __restrict__ ei_u32) {
    int all_zero = 1;
    #pragma unroll
    for (int i = 0; i < 8; i++) {
        if (ei_u32[2 * i + 1] != 0u) all_zero = 0;
    }
    g_is64 = all_zero;
}

__global__ void k_zero_cnt() {
    int i = blockIdx.x * blockDim.x + threadIdx.x;
    if (i < N_NODES) g_cnt[i] = 0;
}

__device__ __forceinline__ void load_edge(const void* ei_raw, int e, int& s, int& d) {
    if (g_is64) {
        const long long* ei = (const long long*)ei_raw;
        s = (int)ei[e];
        d = (int)ei[N_EDGES + e];
    } else {
        const int* ei = (const int*)ei_raw;
        s = ei[e];
        d = ei[N_EDGES + e];
    }
}

__global__ void k_count(const void* __restrict__ ei_raw) {
    int e = blockIdx.x * blockDim.x + threadIdx.x;
    if (e >= N_EDGES) return;
    int s, d;
    load_edge(ei_raw, e, s, d);
    atomicAdd(&g_cnt[d], 1);
}

__global__ void k_dinv() {
    int i = blockIdx.x * blockDim.x + threadIdx.x;
    if (i < N_NODES) g_dinv[i] = rsqrtf((float)g_cnt[i] + 1.0f);  // +1 self loop
}

// ---------------- exclusive scan of g_cnt -> g_rowptr -------------------------
// pass 1: per-block local exclusive prefix + block total
__global__ __launch_bounds__(256) void k_scan1() {
    __shared__ int wsum[8];
    int bid = blockIdx.x, tid = threadIdx.x;
    int lane = tid & 31, wid = tid >> 5;
    int base = bid * SCAN_BLK + tid * 4;

    int v[4];
    #pragma unroll
    for (int i = 0; i < 4; i++) {
        int idx = base + i;
        v[i] = (idx < N_NODES) ? g_cnt[idx] : 0;
    }
    int t1 = v[0] + v[1];
    int t2 = t1 + v[2];
    int tot = t2 + v[3];

    // inclusive warp scan of tot
    int x = tot;
    #pragma unroll
    for (int o = 1; o < 32; o <<= 1) {
        int y = __shfl_up_sync(0xFFFFFFFFu, x, o);
        if (lane >= o) x += y;
    }
    if (lane == 31) wsum[wid] = x;
    __syncthreads();
    if (wid == 0) {
        int w = (lane < 8) ? wsum[lane] : 0;
        #pragma unroll
        for (int o = 1; o < 8; o <<= 1) {
            int y = __shfl_up_sync(0xFFFFFFFFu, w, o);
            if (lane >= o) w += y;
        }
        if (lane < 8) wsum[lane] = w;   // inclusive warp sums
        if (lane == 7) g_bsum[bid] = w; // block total
    }
    __syncthreads();

    int thread_excl = x - tot + (wid > 0 ? wsum[wid - 1] : 0);
    int p[4] = {thread_excl, thread_excl + v[0], thread_excl + t1, thread_excl + t2};
    #pragma unroll
    for (int i = 0; i < 4; i++) {
        int idx = base + i;
        if (idx < N_NODES) g_rowptr[idx] = p[i];
    }
}

// pass 2: exclusive scan of block sums (single block; SCAN_NBLK <= 128)
__global__ __launch_bounds__(128) void k_scan2() {
    __shared__ int wsum[4];
    int tid = threadIdx.x, lane = tid & 31, wid = tid >> 5;
    int v = (tid < SCAN_NBLK) ? g_bsum[tid] : 0;
    int x = v;
    #pragma unroll
    for (int o = 1; o < 32; o <<= 1) {
        int y = __shfl_up_sync(0xFFFFFFFFu, x, o);
        if (lane >= o) x += y;
    }
    if (lane == 31) wsum[wid] = x;
    __syncthreads();
    int add = 0;
    for (int i = 0; i < wid; i++) add += wsum[i];
    if (tid < SCAN_NBLK) g_boff[tid] = x - v + add;
}

// pass 3: add block offsets; copy to cursor; set sentinel
__global__ void k_scan3() {
    int i = blockIdx.x * blockDim.x + threadIdx.x;
    if (i < N_NODES) {
        int r = g_rowptr[i] + g_boff[i >> 10];
        g_rowptr[i] = r;
        g_pos[i] = r;
    }
    if (i == 0) g_rowptr[N_NODES] = N_EDGES;
}

// fill CSR: src index + edge weight, grouped by dst
__global__ void k_scatter(const void* __restrict__ ei_raw) {
    int e = blockIdx.x * blockDim.x + threadIdx.x;
    if (e >= N_EDGES) return;
    int s, d;
    load_edge(ei_raw, e, s, d);
    int p = atomicAdd(&g_pos[d], 1);
    g_csrc[p] = s;
    g_cw[p] = g_dinv[s] * g_dinv[d];
}

// ---------------- GEMM1 (tensor core tf32): g_h = x @ W1 ---------------------
#define BM 128
#define BK 32
#define A_PAD 36
#define B_PAD 132

__device__ __forceinline__ unsigned f2tf(float f) {
    unsigned r;
    asm("cvt.rna.tf32.f32 %0, %1;" : "=r"(r) : "f"(f));
    return r;
}

__device__ __forceinline__ void mma_tf32(float c[4], const unsigned a[4], const unsigned b[2]) {
    asm volatile(
        "mma.sync.aligned.m16n8k8.row.col.f32.tf32.tf32.f32 "
        "{%0,%1,%2,%3}, {%4,%5,%6,%7}, {%8,%9}, {%0,%1,%2,%3};"
        : "+f"(c[0]), "+f"(c[1]), "+f"(c[2]), "+f"(c[3])
        : "r"(a[0]), "r"(a[1]), "r"(a[2]), "r"(a[3]), "r"(b[0]), "r"(b[1]));
}

__global__ __launch_bounds__(256, 2) void k_gemm1_tc(const float* __restrict__ X,
                                                     const float* __restrict__ W) {
    __shared__ unsigned As[BM][A_PAD];   // As[m][k]
    __shared__ unsigned Bs[BK][B_PAD];   // Bs[k][n]

    const int tid = threadIdx.x;
    const int wid = tid >> 5;
    const int lane = tid & 31;
    const int g  = lane >> 2;
    const int tg = lane & 3;
    const int wm = wid >> 2;
    const int wn = wid & 3;
    const int mBase = wm * 64;
    const int nBase = wn * 32;
    const int rowBase = blockIdx.x * BM;

    float c[4][4][4];
    #pragma unroll
    for (int mi = 0; mi < 4; mi++)
        #pragma unroll
        for (int ni = 0; ni < 4; ni++)
            #pragma unroll
            for (int r = 0; r < 4; r++) c[mi][ni][r] = 0.0f;

    for (int k0 = 0; k0 < N_FEAT; k0 += BK) {
        #pragma unroll
        for (int i = 0; i < 4; i++) {
            int slot = tid + i * 256;
            int m  = slot >> 3;
            int kq = slot & 7;
            float4 v = make_float4(0.f, 0.f, 0.f, 0.f);
            int gr = rowBase + m;
            if (gr < N_NODES)
                v = *(const float4*)&X[(size_t)gr * N_FEAT + k0 + kq * 4];
            unsigned* p = &As[m][kq * 4];
            p[0] = f2tf(v.x); p[1] = f2tf(v.y); p[2] = f2tf(v.z); p[3] = f2tf(v.w);
        }
        #pragma unroll
        for (int i = 0; i < 4; i++) {
            int slot = tid + i * 256;
            int kk = slot >> 5;
            int nq = slot & 31;
            float4 v = *(const float4*)&W[(size_t)(k0 + kk) * HIDDEN + nq * 4];
            unsigned* p = &Bs[kk][nq * 4];
            p[0] = f2tf(v.x); p[1] = f2tf(v.y); p[2] = f2tf(v.z); p[3] = f2tf(v.w);
        }
        __syncthreads();

        #pragma unroll
        for (int ks = 0; ks < 4; ks++) {
            const int kb = ks * 8;
            unsigned a[4][4];
            #pragma unroll
            for (int mi = 0; mi < 4; mi++) {
                int r0 = mBase + mi * 16 + g;
                a[mi][0] = As[r0    ][kb + tg];
                a[mi][1] = As[r0 + 8][kb + tg];
                a[mi][2] = As[r0    ][kb + tg + 4];
                a[mi][3] = As[r0 + 8][kb + tg + 4];
            }
            unsigned b[4][2];
            #pragma unroll
            for (int ni = 0; ni < 4; ni++) {
                int col = nBase + ni * 8 + g;
                b[ni][0] = Bs[kb + tg    ][col];
                b[ni][1] = Bs[kb + tg + 4][col];
            }
            #pragma unroll
            for (int mi = 0; mi < 4; mi++)
                #pragma unroll
                for (int ni = 0; ni < 4; ni++)
                    mma_tf32(c[mi][ni], a[mi], b[ni]);
        }
        __syncthreads();
    }

    #pragma unroll
    for (int mi = 0; mi < 4; mi++) {
        int r0 = rowBase + mBase + mi * 16 + g;
        #pragma unroll
        for (int ni = 0; ni < 4; ni++) {
            int col = nBase + ni * 8 + tg * 2;
            if (r0 < N_NODES)
                *(float2*)&g_h[(size_t)r0 * HIDDEN + col] = make_float2(c[mi][ni][0], c[mi][ni][1]);
            if (r0 + 8 < N_NODES)
                *(float2*)&g_h[(size_t)(r0 + 8) * HIDDEN + col] = make_float2(c[mi][ni][2], c[mi][ni][3]);
        }
    }
}

// ---------------- aggregation layer 1: CSR gather, warp per node --------------
__global__ __launch_bounds__(256) void k_agg1_g() {
    int t = blockIdx.x * blockDim.x + threadIdx.x;
    int n = t >> 5;
    if (n >= N_NODES) return;
    int lane = t & 31;

    float di = g_dinv[n];
    float4 acc = *(const float4*)&g_h[(size_t)n * HIDDEN + lane * 4];
    float ws = di * di;                       // self-loop weight
    acc.x *= ws; acc.y *= ws; acc.z *= ws; acc.w *= ws;

    int e   = g_rowptr[n];
    int end = g_rowptr[n + 1];

    for (; e + 1 < end; e += 2) {
        int s0 = g_csrc[e];     float w0 = g_cw[e];
        int s1 = g_csrc[e + 1]; float w1 = g_cw[e + 1];
        float4 v0 = *(const float4*)&g_h[(size_t)s0 * HIDDEN + lane * 4];
        float4 v1 = *(const float4*)&g_h[(size_t)s1 * HIDDEN + lane * 4];
        acc.x = fmaf(v0.x, w0, acc.x); acc.y = fmaf(v0.y, w0, acc.y);
        acc.z = fmaf(v0.z, w0, acc.z); acc.w = fmaf(v0.w, w0, acc.w);
        acc.x = fmaf(v1.x, w1, acc.x); acc.y = fmaf(v1.y, w1, acc.y);
        acc.z = fmaf(v1.z, w1, acc.z); acc.w = fmaf(v1.w, w1, acc.w);
    }
    if (e < end) {
        int s0 = g_csrc[e]; float w0 = g_cw[e];
        float4 v0 = *(const float4*)&g_h[(size_t)s0 * HIDDEN + lane * 4];
        acc.x = fmaf(v0.x, w0, acc.x); acc.y = fmaf(v0.y, w0, acc.y);
        acc.z = fmaf(v0.z, w0, acc.z); acc.w = fmaf(v0.w, w0, acc.w);
    }
    *(float4*)&g_a1[(size_t)n * HIDDEN + lane * 4] = acc;
}

// ---------------- GEMM2: g_h2 = relu(a1 + b1) @ W2  [N,128]@[128,40] ----------
#define G2_ROWS 32
__global__ __launch_bounds__(256) void k_gemm2(const float* __restrict__ W2,
                                               const float* __restrict__ b1) {
    __shared__ float sW[HIDDEN * N_CLASS];
    __shared__ float sH[G2_ROWS][HIDDEN + 4];

    int tid = threadIdx.x;
    for (int i = tid; i < HIDDEN * N_CLASS; i += 256) sW[i] = W2[i];

    int rowBase = blockIdx.x * G2_ROWS;
    for (int i = tid; i < G2_ROWS * HIDDEN; i += 256) {
        int r = i >> 7;
        int k = i & 127;
        int gr = rowBase + r;
        float v = 0.0f;
        if (gr < N_NODES) v = g_a1[(size_t)gr * HIDDEN + k] + b1[k];
        sH[r][k] = fmaxf(v, 0.0f);
    }
    __syncthreads();

    for (int o = tid; o < G2_ROWS * N_CLASS; o += 256) {
        int r = o / N_CLASS;
        int c = o % N_CLASS;
        float acc = 0.0f;
        #pragma unroll 8
        for (int k = 0; k < HIDDEN; k++)
            acc = fmaf(sH[r][k], sW[k * N_CLASS + c], acc);
        int gr = rowBase + r;
        if (gr < N_NODES) g_h2[(size_t)gr * N_CLASS + c] = acc;
    }
}

// ---------------- aggregation layer 2: CSR gather, 10 threads/node ------------
__global__ __launch_bounds__(256) void k_agg2_g() {
    int t = blockIdx.x * blockDim.x + threadIdx.x;
    int n = t / 10;
    if (n >= N_NODES) return;
    int q = t % 10;

    float di = g_dinv[n];
    float ws = di * di;
    float4 acc = *(const float4*)&g_h2[(size_t)n * N_CLASS + q * 4];
    acc.x *= ws; acc.y *= ws; acc.z *= ws; acc.w *= ws;

    int e   = g_rowptr[n];
    int end = g_rowptr[n + 1];
    for (; e < end; e++) {
        int s = g_csrc[e]; float w = g_cw[e];
        float4 v = *(const float4*)&g_h2[(size_t)s * N_CLASS + q * 4];
        acc.x = fmaf(v.x, w, acc.x); acc.y = fmaf(v.y, w, acc.y);
        acc.z = fmaf(v.z, w, acc.z); acc.w = fmaf(v.w, w, acc.w);
    }
    *(float4*)&g_a2[(size_t)n * N_CLASS + q * 4] = acc;
}

// ---------------- log_softmax(a2 + b2) -> out --------------------------------
__global__ void k_lsm(const float* __restrict__ b2, float* __restrict__ out) {
    int r = blockIdx.x * 4 + (threadIdx.x >> 5);
    if (r >= N_NODES) return;
    int lane = threadIdx.x & 31;

    float x0 = g_a2[(size_t)r * N_CLASS + lane] + b2[lane];
    float x1 = -1e30f;
    if (lane < 8) x1 = g_a2[(size_t)r * N_CLASS + 32 + lane] + b2[32 + lane];

    float m = fmaxf(x0, x1);
    #pragma unroll
    for (int o = 16; o > 0; o >>= 1) m = fmaxf(m, __shfl_xor_sync(0xFFFFFFFFu, m, o));

    float s = expf(x0 - m) + ((lane < 8) ? expf(x1 - m) : 0.0f);
    #pragma unroll
    for (int o = 16; o > 0; o >>= 1) s += __shfl_xor_sync(0xFFFFFFFFu, s, o);

    float ls = m + logf(s);
    out[(size_t)r * N_CLASS + lane] = x0 - ls;
    if (lane < 8) out[(size_t)r * N_CLASS + 32 + lane] = x1 - ls;
}

// ---------------- launcher ----------------------------------------------------
extern "C" void kernel_launch(void* const* d_in, const int* in_sizes, int n_in,
                              void* d_out, int out_size) {
    const float* x  = (const float*)d_in[0];
    const void*  ei = d_in[1];
    const float* W1 = (const float*)d_in[2];
    const float* b1 = (const float*)d_in[3];
    const float* W2 = (const float*)d_in[4];
    const float* b2 = (const float*)d_in[5];
    float* out = (float*)d_out;

    k_detect<<<1, 1>>>((const unsigned*)ei);
    k_zero_cnt<<<(N_NODES + 255) / 256, 256>>>();
    k_count<<<(N_EDGES + 255) / 256, 256>>>(ei);
    k_dinv<<<(N_NODES + 255) / 256, 256>>>();
    k_scan1<<<SCAN_NBLK, 256>>>();
    k_scan2<<<1, 128>>>();
    k_scan3<<<(N_NODES + 255) / 256, 256>>>();
    k_scatter<<<(N_EDGES + 255) / 256, 256>>>(ei);

    k_gemm1_tc<<<(N_NODES + BM - 1) / BM, 256>>>(x, W1);
    k_agg1_g<<<(N_NODES * 32 + 255) / 256, 256>>>();

    k_gemm2<<<(N_NODES + G2_ROWS - 1) / G2_ROWS, 256>>>(W2, b1);
    k_agg2_g<<<(N_NODES * 10 + 255) / 256, 256>>>();

    k_lsm<<<(N_NODES + 3) / 4, 128>>>(b2, out);
}

// round 8
// speedup vs baseline: 3.0466x; 1.6062x over previous
#include <cuda_runtime.h>
#include <cuda_bf16.h>
#include <math.h>

// Problem constants (fixed by the dataset)
#define N_NODES  100000
#define N_EDGES  1600000
#define N_FEAT   512
#define HIDDEN   128
#define N_CLASS  40

#define SCAN_BLK   1024
#define SCAN_NBLK  ((N_NODES + SCAN_BLK - 1) / SCAN_BLK)   // 98

// ---------------- scratch (device globals; no cudaMalloc allowed) ------------
__device__ __align__(16) int      g_cnt   [N_NODES];
__device__ __align__(16) float    g_dinv  [N_NODES];
__device__ __align__(16) int      g_rowptr[N_NODES + 1];
__device__ __align__(16) int      g_pos   [N_NODES];
__device__ __align__(16) int      g_bsum  [SCAN_NBLK];
__device__ __align__(16) int      g_boff  [SCAN_NBLK];
__device__ __align__(16) int      g_csrc  [N_EDGES];
__device__ __align__(16) float    g_cw    [N_EDGES];
__device__ __align__(16) unsigned g_hp  [(size_t)N_NODES * (HIDDEN / 2)];   // x@W1, bf16x2
__device__ __align__(16) unsigned g_a1p [(size_t)N_NODES * (HIDDEN / 2)];   // relu(agg1+b1), bf16x2
__device__ __align__(16) unsigned g_h2p [(size_t)N_NODES * (N_CLASS / 2)];  // a1'@W2, bf16x2
__device__ __align__(16) float    g_a2  [(size_t)N_NODES * N_CLASS];        // aggregated logits fp32
__device__ int g_is64;

// ---------------- small helpers ----------------------------------------------
__device__ __forceinline__ void cp16(void* smem, const void* g, int sz) {
    unsigned sa = (unsigned)__cvta_generic_to_shared(smem);
    asm volatile("cp.async.cg.shared.global [%0], [%1], 16, %2;" :: "r"(sa), "l"(g), "r"(sz));
}
__device__ __forceinline__ void cp_commit() { asm volatile("cp.async.commit_group;"); }

__device__ __forceinline__ unsigned pack_bf16(float lo, float hi) {
    __nv_bfloat162 t = __float22bfloat162_rn(make_float2(lo, hi));
    return *reinterpret_cast<unsigned*>(&t);
}
__device__ __forceinline__ float2 unpack_bf16(unsigned u) {
    __nv_bfloat162 t = *reinterpret_cast<__nv_bfloat162*>(&u);
    return __bfloat1622float2(t);
}

// ---------------- dtype detection -------------------------------------------
__global__ void k_detect(const unsigned* __restrict__ ei_u32) {
    int all_zero = 1;
    #pragma unroll
    for (int i = 0; i < 8; i++) {
        if (ei_u32[2 * i + 1] != 0u) all_zero = 0;
    }
    g_is64 = all_zero;
}

__global__ void k_zero_cnt() {
    int i = blockIdx.x * blockDim.x + threadIdx.x;
    if (i < N_NODES) g_cnt[i] = 0;
}

__device__ __forceinline__ void load_edge(const void* ei_raw, int e, int& s, int& d) {
    if (g_is64) {
        const long long* ei = (const long long*)ei_raw;
        s = (int)ei[e];
        d = (int)ei[N_EDGES + e];
    } else {
        const int* ei = (const int*)ei_raw;
        s = ei[e];
        d = ei[N_EDGES + e];
    }
}

__global__ void k_count(const void* __restrict__ ei_raw) {
    int e = blockIdx.x * blockDim.x + threadIdx.x;
    if (e >= N_EDGES) return;
    int s, d;
    load_edge(ei_raw, e, s, d);
    atomicAdd(&g_cnt[d], 1);
}

__global__ void k_dinv() {
    int i = blockIdx.x * blockDim.x + threadIdx.x;
    if (i < N_NODES) g_dinv[i] = rsqrtf((float)g_cnt[i] + 1.0f);
}

// ---------------- exclusive scan of g_cnt -> g_rowptr -------------------------
__global__ __launch_bounds__(256) void k_scan1() {
    __shared__ int wsum[8];
    int bid = blockIdx.x, tid = threadIdx.x;
    int lane = tid & 31, wid = tid >> 5;
    int base = bid * SCAN_BLK + tid * 4;

    int v[4];
    #pragma unroll
    for (int i = 0; i < 4; i++) {
        int idx = base + i;
        v[i] = (idx < N_NODES) ? g_cnt[idx] : 0;
    }
    int t1 = v[0] + v[1];
    int t2 = t1 + v[2];
    int tot = t2 + v[3];

    int x = tot;
    #pragma unroll
    for (int o = 1; o < 32; o <<= 1) {
        int y = __shfl_up_sync(0xFFFFFFFFu, x, o);
        if (lane >= o) x += y;
    }
    if (lane == 31) wsum[wid] = x;
    __syncthreads();
    if (wid == 0) {
        int w = (lane < 8) ? wsum[lane] : 0;
        #pragma unroll
        for (int o = 1; o < 8; o <<= 1) {
            int y = __shfl_up_sync(0xFFFFFFFFu, w, o);
            if (lane >= o) w += y;
        }
        if (lane < 8) wsum[lane] = w;
        if (lane == 7) g_bsum[bid] = w;
    }
    __syncthreads();

    int thread_excl = x - tot + (wid > 0 ? wsum[wid - 1] : 0);
    int p[4] = {thread_excl, thread_excl + v[0], thread_excl + t1, thread_excl + t2};
    #pragma unroll
    for (int i = 0; i < 4; i++) {
        int idx = base + i;
        if (idx < N_NODES) g_rowptr[idx] = p[i];
    }
}

__global__ __launch_bounds__(128) void k_scan2() {
    __shared__ int wsum[4];
    int tid = threadIdx.x, lane = tid & 31, wid = tid >> 5;
    int v = (tid < SCAN_NBLK) ? g_bsum[tid] : 0;
    int x = v;
    #pragma unroll
    for (int o = 1; o < 32; o <<= 1) {
        int y = __shfl_up_sync(0xFFFFFFFFu, x, o);
        if (lane >= o) x += y;
    }
    if (lane == 31) wsum[wid] = x;
    __syncthreads();
    int add = 0;
    for (int i = 0; i < wid; i++) add += wsum[i];
    if (tid < SCAN_NBLK) g_boff[tid] = x - v + add;
}

__global__ void k_scan3() {
    int i = blockIdx.x * blockDim.x + threadIdx.x;
    if (i < N_NODES) {
        int r = g_rowptr[i] + g_boff[i >> 10];
        g_rowptr[i] = r;
        g_pos[i] = r;
    }
    if (i == 0) g_rowptr[N_NODES] = N_EDGES;
}

__global__ void k_scatter(const void* __restrict__ ei_raw) {
    int e = blockIdx.x * blockDim.x + threadIdx.x;
    if (e >= N_EDGES) return;
    int s, d;
    load_edge(ei_raw, e, s, d);
    int p = atomicAdd(&g_pos[d], 1);
    g_csrc[p] = s;
    g_cw[p] = g_dinv[s] * g_dinv[d];
}

// ---------------- GEMM1 (tf32 mma + cp.async double buffer) -------------------
// g_hp = bf16(x @ W1). Block 128x128, BK=32, 8 warps (2M x 4N), warp 64x32.
#define BM 128
#define BK 32
#define A_PAD 36
#define B_PAD 132
#define G1_SMEM ((2 * BM * A_PAD + 2 * BK * B_PAD) * 4)   // 70656 bytes

__device__ __forceinline__ void mma_tf32(float c[4], const unsigned a[4], const unsigned b[2]) {
    asm volatile(
        "mma.sync.aligned.m16n8k8.row.col.f32.tf32.tf32.f32 "
        "{%0,%1,%2,%3}, {%4,%5,%6,%7}, {%8,%9}, {%0,%1,%2,%3};"
        : "+f"(c[0]), "+f"(c[1]), "+f"(c[2]), "+f"(c[3])
        : "r"(a[0]), "r"(a[1]), "r"(a[2]), "r"(a[3]), "r"(b[0]), "r"(b[1]));
}

__global__ __launch_bounds__(256, 2) void k_gemm1_tc(const float* __restrict__ X,
                                                     const float* __restrict__ W) {
    extern __shared__ unsigned dynsmem[];
    unsigned* Asm = dynsmem;                      // [2][BM][A_PAD]
    unsigned* Bsm = dynsmem + 2 * BM * A_PAD;     // [2][BK][B_PAD]
    #define AS(b, m, k) Asm[(b) * BM * A_PAD + (m) * A_PAD + (k)]
    #define BS(b, k, n) Bsm[(b) * BK * B_PAD + (k) * B_PAD + (n)]

    const int tid = threadIdx.x;
    const int wid = tid >> 5;
    const int lane = tid & 31;
    const int g  = lane >> 2;
    const int tg = lane & 3;
    const int wm = wid >> 2;
    const int wn = wid & 3;
    const int mBase = wm * 64;
    const int nBase = wn * 32;
    const int rowBase = blockIdx.x * BM;

    float c[4][4][4];
    #pragma unroll
    for (int mi = 0; mi < 4; mi++)
        #pragma unroll
        for (int ni = 0; ni < 4; ni++)
            #pragma unroll
            for (int r = 0; r < 4; r++) c[mi][ni][r] = 0.0f;

    // tile loader: A = X rows (fp32 bits, tf32 truncation), B = W rows
    auto load_tiles = [&](int buf, int k0) {
        #pragma unroll
        for (int i = 0; i < 4; i++) {
            int slot = tid + i * 256;
            int m  = slot >> 3;
            int kq = slot & 7;
            int gr = rowBase + m;
            int valid = (gr < N_NODES);
            const float* src = X + (size_t)(valid ? gr : 0) * N_FEAT + k0 + kq * 4;
            cp16(&AS(buf, m, kq * 4), src, valid ? 16 : 0);
        }
        #pragma unroll
        for (int i = 0; i < 4; i++) {
            int slot = tid + i * 256;
            int kk = slot >> 5;
            int nq = slot & 31;
            cp16(&BS(buf, kk, nq * 4), W + (size_t)(k0 + kk) * HIDDEN + nq * 4, 16);
        }
        cp_commit();
    };

    load_tiles(0, 0);

    const int NIT = N_FEAT / BK;   // 16
    for (int it = 0; it < NIT; it++) {
        int cur = it & 1;
        if (it < NIT - 1) load_tiles(cur ^ 1, (it + 1) * BK);
        if (it < NIT - 1) { asm volatile("cp.async.wait_group 1;" ::: "memory"); }
        else              { asm volatile("cp.async.wait_group 0;" ::: "memory"); }
        __syncthreads();

        #pragma unroll
        for (int ks = 0; ks < 4; ks++) {
            const int kb = ks * 8;
            unsigned a[4][4];
            #pragma unroll
            for (int mi = 0; mi < 4; mi++) {
                int r0 = mBase + mi * 16 + g;
                a[mi][0] = AS(cur, r0,     kb + tg);
                a[mi][1] = AS(cur, r0 + 8, kb + tg);
                a[mi][2] = AS(cur, r0,     kb + tg + 4);
                a[mi][3] = AS(cur, r0 + 8, kb + tg + 4);
            }
            unsigned b[4][2];
            #pragma unroll
            for (int ni = 0; ni < 4; ni++) {
                int col = nBase + ni * 8 + g;
                b[ni][0] = BS(cur, kb + tg,     col);
                b[ni][1] = BS(cur, kb + tg + 4, col);
            }
            #pragma unroll
            for (int mi = 0; mi < 4; mi++)
                #pragma unroll
                for (int ni = 0; ni < 4; ni++)
                    mma_tf32(c[mi][ni], a[mi], b[ni]);
        }
        __syncthreads();
    }

    // epilogue -> bf16 pairs
    #pragma unroll
    for (int mi = 0; mi < 4; mi++) {
        int r0 = rowBase + mBase + mi * 16 + g;
        #pragma unroll
        for (int ni = 0; ni < 4; ni++) {
            int colu = (nBase + ni * 8) / 2 + tg;   // uint col (64 per row)
            if (r0 < N_NODES)
                g_hp[(size_t)r0 * 64 + colu] = pack_bf16(c[mi][ni][0], c[mi][ni][1]);
            if (r0 + 8 < N_NODES)
                g_hp[(size_t)(r0 + 8) * 64 + colu] = pack_bf16(c[mi][ni][2], c[mi][ni][3]);
        }
    }
    #undef AS
    #undef BS
}

// ---------------- agg1: CSR gather (bf16 in) + bias + relu -> bf16 out --------
__global__ __launch_bounds__(256) void k_agg1_g(const float* __restrict__ b1) {
    int t = blockIdx.x * blockDim.x + threadIdx.x;
    int n = t >> 5;
    if (n >= N_NODES) return;
    int lane = t & 31;

    float di = g_dinv[n];
    float ws = di * di;

    uint2 su = *(const uint2*)&g_hp[(size_t)n * 64 + 2 * lane];
    float2 s0 = unpack_bf16(su.x), s1 = unpack_bf16(su.y);
    float4 acc = make_float4(s0.x * ws, s0.y * ws, s1.x * ws, s1.y * ws);

    int e   = g_rowptr[n];
    int end = g_rowptr[n + 1];

    for (; e + 1 < end; e += 2) {
        int sa = g_csrc[e];     float w0 = g_cw[e];
        int sb = g_csrc[e + 1]; float w1 = g_cw[e + 1];
        uint2 ua = *(const uint2*)&g_hp[(size_t)sa * 64 + 2 * lane];
        uint2 ub = *(const uint2*)&g_hp[(size_t)sb * 64 + 2 * lane];
        float2 a0 = unpack_bf16(ua.x), a1v = unpack_bf16(ua.y);
        float2 bb0 = unpack_bf16(ub.x), bb1 = unpack_bf16(ub.y);
        acc.x = fmaf(a0.x, w0, acc.x); acc.y = fmaf(a0.y, w0, acc.y);
        acc.z = fmaf(a1v.x, w0, acc.z); acc.w = fmaf(a1v.y, w0, acc.w);
        acc.x = fmaf(bb0.x, w1, acc.x); acc.y = fmaf(bb0.y, w1, acc.y);
        acc.z = fmaf(bb1.x, w1, acc.z); acc.w = fmaf(bb1.y, w1, acc.w);
    }
    if (e < end) {
        int sa = g_csrc[e]; float w0 = g_cw[e];
        uint2 ua = *(const uint2*)&g_hp[(size_t)sa * 64 + 2 * lane];
        float2 a0 = unpack_bf16(ua.x), a1v = unpack_bf16(ua.y);
        acc.x = fmaf(a0.x, w0, acc.x); acc.y = fmaf(a0.y, w0, acc.y);
        acc.z = fmaf(a1v.x, w0, acc.z); acc.w = fmaf(a1v.y, w0, acc.w);
    }

    float4 bv = *(const float4*)&b1[lane * 4];
    acc.x = fmaxf(acc.x + bv.x, 0.0f);
    acc.y = fmaxf(acc.y + bv.y, 0.0f);
    acc.z = fmaxf(acc.z + bv.z, 0.0f);
    acc.w = fmaxf(acc.w + bv.w, 0.0f);

    uint2 o;
    o.x = pack_bf16(acc.x, acc.y);
    o.y = pack_bf16(acc.z, acc.w);
    *(uint2*)&g_a1p[(size_t)n * 64 + 2 * lane] = o;
}

// ---------------- GEMM2 (bf16 mma): g_h2p = a1' @ W2  [N,128]@[128,40] --------
// Block 128 rows, 8 warps x m16; N=40 = 5 n8 tiles; K=128 = 8 k16 steps.
#define A2_PAD 68
__global__ __launch_bounds__(256) void k_gemm2_tc(const float* __restrict__ W2) {
    __shared__ unsigned sAp[128][A2_PAD];   // a1' bf16 pairs [row][k/2]
    __shared__ unsigned sBp[64][N_CLASS];   // W2 bf16 pairs  [k/2][n]

    const int tid = threadIdx.x;
    const int wid = tid >> 5;
    const int lane = tid & 31;
    const int g  = lane >> 2;
    const int tg = lane & 3;
    const int rowBase = blockIdx.x * 128;

    // stage W2 -> bf16 pairs (2560 entries)
    for (int i = tid; i < 64 * N_CLASS; i += 256) {
        int k2 = i / N_CLASS, n = i % N_CLASS;
        float lo = W2[(size_t)(2 * k2) * N_CLASS + n];
        float hi = W2[(size_t)(2 * k2 + 1) * N_CLASS + n];
        sBp[k2][n] = pack_bf16(lo, hi);
    }
    // stage a1' tile via cp.async (128 rows x 16 chunks)
    #pragma unroll
    for (int i = 0; i < 8; i++) {
        int slot = tid + i * 256;
        int m = slot >> 4;
        int j = slot & 15;
        int gr = rowBase + m;
        int valid = (gr < N_NODES);
        cp16(&sAp[m][j * 4], g_a1p + (size_t)(valid ? gr : 0) * 64 + j * 4, valid ? 16 : 0);
    }
    cp_commit();
    asm volatile("cp.async.wait_group 0;" ::: "memory");
    __syncthreads();

    const int mBase = wid * 16;
    float c[5][4];
    #pragma unroll
    for (int ni = 0; ni < 5; ni++)
        #pragma unroll
        for (int r = 0; r < 4; r++) c[ni][r] = 0.0f;

    #pragma unroll
    for (int ks = 0; ks < 8; ks++) {
        int k2b = ks * 8;
        int r0 = mBase + g;
        unsigned a0 = sAp[r0    ][k2b + tg];
        unsigned a1 = sAp[r0 + 8][k2b + tg];
        unsigned a2 = sAp[r0    ][k2b + tg + 4];
        unsigned a3 = sAp[r0 + 8][k2b + tg + 4];
        #pragma unroll
        for (int ni = 0; ni < 5; ni++) {
            unsigned b0 = sBp[k2b + tg    ][ni * 8 + g];
            unsigned b1r = sBp[k2b + tg + 4][ni * 8 + g];
            asm volatile(
                "mma.sync.aligned.m16n8k16.row.col.f32.bf16.bf16.f32 "
                "{%0,%1,%2,%3}, {%4,%5,%6,%7}, {%8,%9}, {%0,%1,%2,%3};"
                : "+f"(c[ni][0]), "+f"(c[ni][1]), "+f"(c[ni][2]), "+f"(c[ni][3])
                : "r"(a0), "r"(a1), "r"(a2), "r"(a3), "r"(b0), "r"(b1r));
        }
    }

    // epilogue -> h2 bf16 pairs (20 uints per row)
    int r0 = rowBase + mBase + g;
    #pragma unroll
    for (int ni = 0; ni < 5; ni++) {
        int colu = ni * 4 + tg;
        if (r0 < N_NODES)
            g_h2p[(size_t)r0 * 20 + colu] = pack_bf16(c[ni][0], c[ni][1]);
        if (r0 + 8 < N_NODES)
            g_h2p[(size_t)(r0 + 8) * 20 + colu] = pack_bf16(c[ni][2], c[ni][3]);
    }
}

// ---------------- agg2: CSR gather on bf16 h2, 10 threads/node ----------------
__global__ __launch_bounds__(256) void k_agg2_g() {
    int t = blockIdx.x * blockDim.x + threadIdx.x;
    int n = t / 10;
    if (n >= N_NODES) return;
    int q = t % 10;

    float di = g_dinv[n];
    float ws = di * di;

    uint2 su = *(const uint2*)&g_h2p[(size_t)n * 20 + 2 * q];
    float2 s0 = unpack_bf16(su.x), s1 = unpack_bf16(su.y);
    float4 acc = make_float4(s0.x * ws, s0.y * ws, s1.x * ws, s1.y * ws);

    int e   = g_rowptr[n];
    int end = g_rowptr[n + 1];
    for (; e < end; e++) {
        int s = g_csrc[e]; float w = g_cw[e];
        uint2 u = *(const uint2*)&g_h2p[(size_t)s * 20 + 2 * q];
        float2 v0 = unpack_bf16(u.x), v1 = unpack_bf16(u.y);
        acc.x = fmaf(v0.x, w, acc.x); acc.y = fmaf(v0.y, w, acc.y);
        acc.z = fmaf(v1.x, w, acc.z); acc.w = fmaf(v1.y, w, acc.w);
    }
    *(float4*)&g_a2[(size_t)n * N_CLASS + q * 4] = acc;
}

// ---------------- log_softmax(a2 + b2) -> out --------------------------------
__global__ void k_lsm(const float* __restrict__ b2, float* __restrict__ out) {
    int r = blockIdx.x * 4 + (threadIdx.x >> 5);
    if (r >= N_NODES) return;
    int lane = threadIdx.x & 31;

    float x0 = g_a2[(size_t)r * N_CLASS + lane] + b2[lane];
    float x1 = -1e30f;
    if (lane < 8) x1 = g_a2[(size_t)r * N_CLASS + 32 + lane] + b2[32 + lane];

    float m = fmaxf(x0, x1);
    #pragma unroll
    for (int o = 16; o > 0; o >>= 1) m = fmaxf(m, __shfl_xor_sync(0xFFFFFFFFu, m, o));

    float s = expf(x0 - m) + ((lane < 8) ? expf(x1 - m) : 0.0f);
    #pragma unroll
    for (int o = 16; o > 0; o >>= 1) s += __shfl_xor_sync(0xFFFFFFFFu, s, o);

    float ls = m + logf(s);
    out[(size_t)r * N_CLASS + lane] = x0 - ls;
    if (lane < 8) out[(size_t)r * N_CLASS + 32 + lane] = x1 - ls;
}

// ---------------- launcher ----------------------------------------------------
extern "C" void kernel_launch(void* const* d_in, const int* in_sizes, int n_in,
                              void* d_out, int out_size) {
    const float* x  = (const float*)d_in[0];
    const void*  ei = d_in[1];
    const float* W1 = (const float*)d_in[2];
    const float* b1 = (const float*)d_in[3];
    const float* W2 = (const float*)d_in[4];
    const float* b2 = (const float*)d_in[5];
    float* out = (float*)d_out;

    cudaFuncSetAttribute(k_gemm1_tc, cudaFuncAttributeMaxDynamicSharedMemorySize, G1_SMEM);

    k_detect<<<1, 1>>>((const unsigned*)ei);
    k_zero_cnt<<<(N_NODES + 255) / 256, 256>>>();
    k_count<<<(N_EDGES + 255) / 256, 256>>>(ei);
    k_dinv<<<(N_NODES + 255) / 256, 256>>>();
    k_scan1<<<SCAN_NBLK, 256>>>();
    k_scan2<<<1, 128>>>();
    k_scan3<<<(N_NODES + 255) / 256, 256>>>();
    k_scatter<<<(N_EDGES + 255) / 256, 256>>>(ei);

    k_gemm1_tc<<<(N_NODES + BM - 1) / BM, 256, G1_SMEM>>>(x, W1);
    k_agg1_g<<<(N_NODES * 32 + 255) / 256, 256>>>(b1);

    k_gemm2_tc<<<(N_NODES + 127) / 128, 256>>>(W2);
    k_agg2_g<<<(N_NODES * 10 + 255) / 256, 256>>>();

    k_lsm<<<(N_NODES + 3) / 4, 128>>>(b2, out);
}

// round 9
// speedup vs baseline: 3.5810x; 1.1754x over previous
#include <cuda_runtime.h>
#include <cuda_bf16.h>
#include <math.h>

// Problem constants (fixed by the dataset)
#define N_NODES  100000
#define N_EDGES  1600000
#define N_FEAT   512
#define HIDDEN   128
#define N_CLASS  40

#define SCAN_BLK   1024
#define SCAN_NBLK  ((N_NODES + SCAN_BLK - 1) / SCAN_BLK)   // 98

// ---------------- scratch (device globals; no cudaMalloc allowed) ------------
__device__ __align__(16) int      g_cnt   [N_NODES];
__device__ __align__(16) float    g_dinv  [N_NODES];
__device__ __align__(16) int      g_rowptr[N_NODES + 1];
__device__ __align__(16) int      g_pos   [N_NODES];
__device__ __align__(16) int      g_bsum  [SCAN_NBLK];
__device__ __align__(16) int      g_boff  [SCAN_NBLK];
__device__ __align__(16) int      g_csrc  [N_EDGES];
__device__ __align__(16) unsigned g_hp  [(size_t)N_NODES * (HIDDEN / 2)];   // x@W1, bf16x2
__device__ __align__(16) unsigned g_a1p [(size_t)N_NODES * (HIDDEN / 2)];   // relu(agg1+b1), bf16x2
__device__ __align__(16) unsigned g_h2p [(size_t)N_NODES * (N_CLASS / 2)];  // dinv*(a1'@W2), bf16x2
__device__ __align__(16) float    g_a2  [(size_t)N_NODES * N_CLASS];        // aggregated logits fp32
__device__ int g_is64;

// ---------------- small helpers ----------------------------------------------
__device__ __forceinline__ void cp16(void* smem, const void* g, int sz) {
    unsigned sa = (unsigned)__cvta_generic_to_shared(smem);
    asm volatile("cp.async.cg.shared.global [%0], [%1], 16, %2;" :: "r"(sa), "l"(g), "r"(sz));
}
__device__ __forceinline__ void cp_commit() { asm volatile("cp.async.commit_group;"); }

__device__ __forceinline__ unsigned pack_bf16(float lo, float hi) {
    __nv_bfloat162 t = __float22bfloat162_rn(make_float2(lo, hi));
    return *reinterpret_cast<unsigned*>(&t);
}
__device__ __forceinline__ float2 unpack_bf16(unsigned u) {
    __nv_bfloat162 t = *reinterpret_cast<__nv_bfloat162*>(&u);
    return __bfloat1622float2(t);
}

// ---------------- init: detect dtype + zero counters ---------------------------
__global__ void k_init(const unsigned* __restrict__ ei_u32) {
    int i = blockIdx.x * blockDim.x + threadIdx.x;
    if (i < N_NODES) g_cnt[i] = 0;
    if (i == 0) {
        int all_zero = 1;
        #pragma unroll
        for (int j = 0; j < 8; j++)
            if (ei_u32[2 * j + 1] != 0u) all_zero = 0;
        g_is64 = all_zero;
    }
}

__device__ __forceinline__ void load_edge(const void* ei_raw, int e, int& s, int& d) {
    if (g_is64) {
        const long long* ei = (const long long*)ei_raw;
        s = (int)ei[e];
        d = (int)ei[N_EDGES + e];
    } else {
        const int* ei = (const int*)ei_raw;
        s = ei[e];
        d = ei[N_EDGES + e];
    }
}

__global__ void k_count(const void* __restrict__ ei_raw) {
    int e = blockIdx.x * blockDim.x + threadIdx.x;
    if (e >= N_EDGES) return;
    int s, d;
    load_edge(ei_raw, e, s, d);
    atomicAdd(&g_cnt[d], 1);
}

// ---------------- exclusive scan of g_cnt -> g_rowptr (+ fused dinv) ----------
__global__ __launch_bounds__(256) void k_scan1() {
    __shared__ int wsum[8];
    int bid = blockIdx.x, tid = threadIdx.x;
    int lane = tid & 31, wid = tid >> 5;
    int base = bid * SCAN_BLK + tid * 4;

    int v[4];
    #pragma unroll
    for (int i = 0; i < 4; i++) {
        int idx = base + i;
        v[i] = (idx < N_NODES) ? g_cnt[idx] : 0;
        if (idx < N_NODES) g_dinv[idx] = rsqrtf((float)v[i] + 1.0f);
    }
    int t1 = v[0] + v[1];
    int t2 = t1 + v[2];
    int tot = t2 + v[3];

    int x = tot;
    #pragma unroll
    for (int o = 1; o < 32; o <<= 1) {
        int y = __shfl_up_sync(0xFFFFFFFFu, x, o);
        if (lane >= o) x += y;
    }
    if (lane == 31) wsum[wid] = x;
    __syncthreads();
    if (wid == 0) {
        int w = (lane < 8) ? wsum[lane] : 0;
        #pragma unroll
        for (int o = 1; o < 8; o <<= 1) {
            int y = __shfl_up_sync(0xFFFFFFFFu, w, o);
            if (lane >= o) w += y;
        }
        if (lane < 8) wsum[lane] = w;
        if (lane == 7) g_bsum[bid] = w;
    }
    __syncthreads();

    int thread_excl = x - tot + (wid > 0 ? wsum[wid - 1] : 0);
    int p[4] = {thread_excl, thread_excl + v[0], thread_excl + t1, thread_excl + t2};
    #pragma unroll
    for (int i = 0; i < 4; i++) {
        int idx = base + i;
        if (idx < N_NODES) g_rowptr[idx] = p[i];
    }
}

__global__ __launch_bounds__(128) void k_scan2() {
    __shared__ int wsum[4];
    int tid = threadIdx.x, lane = tid & 31, wid = tid >> 5;
    int v = (tid < SCAN_NBLK) ? g_bsum[tid] : 0;
    int x = v;
    #pragma unroll
    for (int o = 1; o < 32; o <<= 1) {
        int y = __shfl_up_sync(0xFFFFFFFFu, x, o);
        if (lane >= o) x += y;
    }
    if (lane == 31) wsum[wid] = x;
    __syncthreads();
    int add = 0;
    for (int i = 0; i < wid; i++) add += wsum[i];
    if (tid < SCAN_NBLK) g_boff[tid] = x - v + add;
}

__global__ void k_scan3() {
    int i = blockIdx.x * blockDim.x + threadIdx.x;
    if (i < N_NODES) {
        int r = g_rowptr[i] + g_boff[i >> 10];
        g_rowptr[i] = r;
        g_pos[i] = r;
    }
    if (i == 0) g_rowptr[N_NODES] = N_EDGES;
}

// fill CSR: src index only (weights factorized into dinv)
__global__ void k_scatter(const void* __restrict__ ei_raw) {
    int e = blockIdx.x * blockDim.x + threadIdx.x;
    if (e >= N_EDGES) return;
    int s, d;
    load_edge(ei_raw, e, s, d);
    int p = atomicAdd(&g_pos[d], 1);
    g_csrc[p] = s;
}

// ---------------- GEMM1 (tf32 mma + cp.async double buffer) -------------------
#define BM 128
#define BK 32
#define A_PAD 36
#define B_PAD 132
#define G1_SMEM ((2 * BM * A_PAD + 2 * BK * B_PAD) * 4)   // 70656 bytes

__device__ __forceinline__ void mma_tf32(float c[4], const unsigned a[4], const unsigned b[2]) {
    asm volatile(
        "mma.sync.aligned.m16n8k8.row.col.f32.tf32.tf32.f32 "
        "{%0,%1,%2,%3}, {%4,%5,%6,%7}, {%8,%9}, {%0,%1,%2,%3};"
        : "+f"(c[0]), "+f"(c[1]), "+f"(c[2]), "+f"(c[3])
        : "r"(a[0]), "r"(a[1]), "r"(a[2]), "r"(a[3]), "r"(b[0]), "r"(b[1]));
}

__global__ __launch_bounds__(256, 2) void k_gemm1_tc(const float* __restrict__ X,
                                                     const float* __restrict__ W) {
    extern __shared__ unsigned dynsmem[];
    unsigned* Asm = dynsmem;                      // [2][BM][A_PAD]
    unsigned* Bsm = dynsmem + 2 * BM * A_PAD;     // [2][BK][B_PAD]
    #define AS(b, m, k) Asm[(b) * BM * A_PAD + (m) * A_PAD + (k)]
    #define BS(b, k, n) Bsm[(b) * BK * B_PAD + (k) * B_PAD + (n)]

    const int tid = threadIdx.x;
    const int wid = tid >> 5;
    const int lane = tid & 31;
    const int g  = lane >> 2;
    const int tg = lane & 3;
    const int wm = wid >> 2;
    const int wn = wid & 3;
    const int mBase = wm * 64;
    const int nBase = wn * 32;
    const int rowBase = blockIdx.x * BM;

    float c[4][4][4];
    #pragma unroll
    for (int mi = 0; mi < 4; mi++)
        #pragma unroll
        for (int ni = 0; ni < 4; ni++)
            #pragma unroll
            for (int r = 0; r < 4; r++) c[mi][ni][r] = 0.0f;

    auto load_tiles = [&](int buf, int k0) {
        #pragma unroll
        for (int i = 0; i < 4; i++) {
            int slot = tid + i * 256;
            int m  = slot >> 3;
            int kq = slot & 7;
            int gr = rowBase + m;
            int valid = (gr < N_NODES);
            const float* src = X + (size_t)(valid ? gr : 0) * N_FEAT + k0 + kq * 4;
            cp16(&AS(buf, m, kq * 4), src, valid ? 16 : 0);
        }
        #pragma unroll
        for (int i = 0; i < 4; i++) {
            int slot = tid + i * 256;
            int kk = slot >> 5;
            int nq = slot & 31;
            cp16(&BS(buf, kk, nq * 4), W + (size_t)(k0 + kk) * HIDDEN + nq * 4, 16);
        }
        cp_commit();
    };

    load_tiles(0, 0);

    const int NIT = N_FEAT / BK;   // 16
    for (int it = 0; it < NIT; it++) {
        int cur = it & 1;
        if (it < NIT - 1) load_tiles(cur ^ 1, (it + 1) * BK);
        if (it < NIT - 1) { asm volatile("cp.async.wait_group 1;" ::: "memory"); }
        else              { asm volatile("cp.async.wait_group 0;" ::: "memory"); }
        __syncthreads();

        #pragma unroll
        for (int ks = 0; ks < 4; ks++) {
            const int kb = ks * 8;
            unsigned a[4][4];
            #pragma unroll
            for (int mi = 0; mi < 4; mi++) {
                int r0 = mBase + mi * 16 + g;
                a[mi][0] = AS(cur, r0,     kb + tg);
                a[mi][1] = AS(cur, r0 + 8, kb + tg);
                a[mi][2] = AS(cur, r0,     kb + tg + 4);
                a[mi][3] = AS(cur, r0 + 8, kb + tg + 4);
            }
            unsigned b[4][2];
            #pragma unroll
            for (int ni = 0; ni < 4; ni++) {
                int col = nBase + ni * 8 + g;
                b[ni][0] = BS(cur, kb + tg,     col);
                b[ni][1] = BS(cur, kb + tg + 4, col);
            }
            #pragma unroll
            for (int mi = 0; mi < 4; mi++)
                #pragma unroll
                for (int ni = 0; ni < 4; ni++)
                    mma_tf32(c[mi][ni], a[mi], b[ni]);
        }
        __syncthreads();
    }

    #pragma unroll
    for (int mi = 0; mi < 4; mi++) {
        int r0 = rowBase + mBase + mi * 16 + g;
        #pragma unroll
        for (int ni = 0; ni < 4; ni++) {
            int colu = (nBase + ni * 8) / 2 + tg;
            if (r0 < N_NODES)
                g_hp[(size_t)r0 * 64 + colu] = pack_bf16(c[mi][ni][0], c[mi][ni][1]);
            if (r0 + 8 < N_NODES)
                g_hp[(size_t)(r0 + 8) * 64 + colu] = pack_bf16(c[mi][ni][2], c[mi][ni][3]);
        }
    }
    #undef AS
    #undef BS
}

// ---------------- agg1: CSR gather, weight = dinv[s]; final *dinv[n] ----------
// a1'[n] = relu(dinv[n]*(sum_s dinv[s]*h[s] + dinv[n]*h[n]) + b1)
__global__ __launch_bounds__(256) void k_agg1_g(const float* __restrict__ b1) {
    int t = blockIdx.x * blockDim.x + threadIdx.x;
    int n = t >> 5;
    if (n >= N_NODES) return;
    int lane = t & 31;

    float wn = g_dinv[n];

    uint2 su = *(const uint2*)&g_hp[(size_t)n * 64 + 2 * lane];
    float2 s0 = unpack_bf16(su.x), s1 = unpack_bf16(su.y);
    float4 acc = make_float4(s0.x * wn, s0.y * wn, s1.x * wn, s1.y * wn);

    int e   = g_rowptr[n];
    int end = g_rowptr[n + 1];

    for (; e + 4 <= end; e += 4) {
        int i0 = g_csrc[e], i1 = g_csrc[e + 1], i2 = g_csrc[e + 2], i3 = g_csrc[e + 3];
        float w0 = g_dinv[i0], w1 = g_dinv[i1], w2 = g_dinv[i2], w3 = g_dinv[i3];
        uint2 u0 = *(const uint2*)&g_hp[(size_t)i0 * 64 + 2 * lane];
        uint2 u1 = *(const uint2*)&g_hp[(size_t)i1 * 64 + 2 * lane];
        uint2 u2 = *(const uint2*)&g_hp[(size_t)i2 * 64 + 2 * lane];
        uint2 u3 = *(const uint2*)&g_hp[(size_t)i3 * 64 + 2 * lane];
        float2 a, b;
        a = unpack_bf16(u0.x); b = unpack_bf16(u0.y);
        acc.x = fmaf(a.x, w0, acc.x); acc.y = fmaf(a.y, w0, acc.y);
        acc.z = fmaf(b.x, w0, acc.z); acc.w = fmaf(b.y, w0, acc.w);
        a = unpack_bf16(u1.x); b = unpack_bf16(u1.y);
        acc.x = fmaf(a.x, w1, acc.x); acc.y = fmaf(a.y, w1, acc.y);
        acc.z = fmaf(b.x, w1, acc.z); acc.w = fmaf(b.y, w1, acc.w);
        a = unpack_bf16(u2.x); b = unpack_bf16(u2.y);
        acc.x = fmaf(a.x, w2, acc.x); acc.y = fmaf(a.y, w2, acc.y);
        acc.z = fmaf(b.x, w2, acc.z); acc.w = fmaf(b.y, w2, acc.w);
        a = unpack_bf16(u3.x); b = unpack_bf16(u3.y);
        acc.x = fmaf(a.x, w3, acc.x); acc.y = fmaf(a.y, w3, acc.y);
        acc.z = fmaf(b.x, w3, acc.z); acc.w = fmaf(b.y, w3, acc.w);
    }
    for (; e < end; e++) {
        int i0 = g_csrc[e];
        float w0 = g_dinv[i0];
        uint2 u0 = *(const uint2*)&g_hp[(size_t)i0 * 64 + 2 * lane];
        float2 a = unpack_bf16(u0.x), b = unpack_bf16(u0.y);
        acc.x = fmaf(a.x, w0, acc.x); acc.y = fmaf(a.y, w0, acc.y);
        acc.z = fmaf(b.x, w0, acc.z); acc.w = fmaf(b.y, w0, acc.w);
    }

    float4 bv = *(const float4*)&b1[lane * 4];
    acc.x = fmaxf(fmaf(acc.x, wn, bv.x), 0.0f);
    acc.y = fmaxf(fmaf(acc.y, wn, bv.y), 0.0f);
    acc.z = fmaxf(fmaf(acc.z, wn, bv.z), 0.0f);
    acc.w = fmaxf(fmaf(acc.w, wn, bv.w), 0.0f);

    uint2 o;
    o.x = pack_bf16(acc.x, acc.y);
    o.y = pack_bf16(acc.z, acc.w);
    *(uint2*)&g_a1p[(size_t)n * 64 + 2 * lane] = o;
}

// ---------------- GEMM2 (bf16 mma): g_h2p = dinv * (a1' @ W2) ------------------
#define A2_PAD 68
__global__ __launch_bounds__(256) void k_gemm2_tc(const float* __restrict__ W2) {
    __shared__ unsigned sAp[128][A2_PAD];
    __shared__ unsigned sBp[64][N_CLASS];

    const int tid = threadIdx.x;
    const int wid = tid >> 5;
    const int lane = tid & 31;
    const int g  = lane >> 2;
    const int tg = lane & 3;
    const int rowBase = blockIdx.x * 128;

    for (int i = tid; i < 64 * N_CLASS; i += 256) {
        int k2 = i / N_CLASS, n = i % N_CLASS;
        float lo = W2[(size_t)(2 * k2) * N_CLASS + n];
        float hi = W2[(size_t)(2 * k2 + 1) * N_CLASS + n];
        sBp[k2][n] = pack_bf16(lo, hi);
    }
    #pragma unroll
    for (int i = 0; i < 8; i++) {
        int slot = tid + i * 256;
        int m = slot >> 4;
        int j = slot & 15;
        int gr = rowBase + m;
        int valid = (gr < N_NODES);
        cp16(&sAp[m][j * 4], g_a1p + (size_t)(valid ? gr : 0) * 64 + j * 4, valid ? 16 : 0);
    }
    cp_commit();
    asm volatile("cp.async.wait_group 0;" ::: "memory");
    __syncthreads();

    const int mBase = wid * 16;
    float c[5][4];
    #pragma unroll
    for (int ni = 0; ni < 5; ni++)
        #pragma unroll
        for (int r = 0; r < 4; r++) c[ni][r] = 0.0f;

    #pragma unroll
    for (int ks = 0; ks < 8; ks++) {
        int k2b = ks * 8;
        int r0 = mBase + g;
        unsigned a0 = sAp[r0    ][k2b + tg];
        unsigned a1 = sAp[r0 + 8][k2b + tg];
        unsigned a2 = sAp[r0    ][k2b + tg + 4];
        unsigned a3 = sAp[r0 + 8][k2b + tg + 4];
        #pragma unroll
        for (int ni = 0; ni < 5; ni++) {
            unsigned b0 = sBp[k2b + tg    ][ni * 8 + g];
            unsigned b1r = sBp[k2b + tg + 4][ni * 8 + g];
            asm volatile(
                "mma.sync.aligned.m16n8k16.row.col.f32.bf16.bf16.f32 "
                "{%0,%1,%2,%3}, {%4,%5,%6,%7}, {%8,%9}, {%0,%1,%2,%3};"
                : "+f"(c[ni][0]), "+f"(c[ni][1]), "+f"(c[ni][2]), "+f"(c[ni][3])
                : "r"(a0), "r"(a1), "r"(a2), "r"(a3), "r"(b0), "r"(b1r));
        }
    }

    // epilogue: scale by dinv[row], pack bf16
    int r0 = rowBase + mBase + g;
    float w0 = (r0 < N_NODES) ? g_dinv[r0] : 0.0f;
    float w1 = (r0 + 8 < N_NODES) ? g_dinv[r0 + 8] : 0.0f;
    #pragma unroll
    for (int ni = 0; ni < 5; ni++) {
        int colu = ni * 4 + tg;
        if (r0 < N_NODES)
            g_h2p[(size_t)r0 * 20 + colu] = pack_bf16(c[ni][0] * w0, c[ni][1] * w0);
        if (r0 + 8 < N_NODES)
            g_h2p[(size_t)(r0 + 8) * 20 + colu] = pack_bf16(c[ni][2] * w1, c[ni][3] * w1);
    }
}

// ---------------- agg2: CSR gather on pre-scaled h2', final *dinv[n] ----------
__global__ __launch_bounds__(256) void k_agg2_g() {
    int t = blockIdx.x * blockDim.x + threadIdx.x;
    int n = t / 10;
    if (n >= N_NODES) return;
    int q = t % 10;

    float wn = g_dinv[n];

    uint2 su = *(const uint2*)&g_h2p[(size_t)n * 20 + 2 * q];
    float2 s0 = unpack_bf16(su.x), s1 = unpack_bf16(su.y);
    float4 acc = make_float4(s0.x, s0.y, s1.x, s1.y);

    int e   = g_rowptr[n];
    int end = g_rowptr[n + 1];
    for (; e + 2 <= end; e += 2) {
        int i0 = g_csrc[e], i1 = g_csrc[e + 1];
        uint2 u0 = *(const uint2*)&g_h2p[(size_t)i0 * 20 + 2 * q];
        uint2 u1 = *(const uint2*)&g_h2p[(size_t)i1 * 20 + 2 * q];
        float2 a = unpack_bf16(u0.x), b = unpack_bf16(u0.y);
        acc.x += a.x; acc.y += a.y; acc.z += b.x; acc.w += b.y;
        a = unpack_bf16(u1.x); b = unpack_bf16(u1.y);
        acc.x += a.x; acc.y += a.y; acc.z += b.x; acc.w += b.y;
    }
    if (e < end) {
        int i0 = g_csrc[e];
        uint2 u0 = *(const uint2*)&g_h2p[(size_t)i0 * 20 + 2 * q];
        float2 a = unpack_bf16(u0.x), b = unpack_bf16(u0.y);
        acc.x += a.x; acc.y += a.y; acc.z += b.x; acc.w += b.y;
    }
    acc.x *= wn; acc.y *= wn; acc.z *= wn; acc.w *= wn;
    *(float4*)&g_a2[(size_t)n * N_CLASS + q * 4] = acc;
}

// ---------------- log_softmax(a2 + b2) -> out --------------------------------
__global__ void k_lsm(const float* __restrict__ b2, float* __restrict__ out) {
    int r = blockIdx.x * 4 + (threadIdx.x >> 5);
    if (r >= N_NODES) return;
    int lane = threadIdx.x & 31;

    float x0 = g_a2[(size_t)r * N_CLASS + lane] + b2[lane];
    float x1 = -1e30f;
    if (lane < 8) x1 = g_a2[(size_t)r * N_CLASS + 32 + lane] + b2[32 + lane];

    float m = fmaxf(x0, x1);
    #pragma unroll
    for (int o = 16; o > 0; o >>= 1) m = fmaxf(m, __shfl_xor_sync(0xFFFFFFFFu, m, o));

    float s = expf(x0 - m) + ((lane < 8) ? expf(x1 - m) : 0.0f);
    #pragma unroll
    for (int o = 16; o > 0; o >>= 1) s += __shfl_xor_sync(0xFFFFFFFFu, s, o);

    float ls = m + logf(s);
    out[(size_t)r * N_CLASS + lane] = x0 - ls;
    if (lane < 8) out[(size_t)r * N_CLASS + 32 + lane] = x1 - ls;
}

// ---------------- launcher: fork-join (prep || gemm1) --------------------------
extern "C" void kernel_launch(void* const* d_in, const int* in_sizes, int n_in,
                              void* d_out, int out_size) {
    const float* x  = (const float*)d_in[0];
    const void*  ei = d_in[1];
    const float* W1 = (const float*)d_in[2];
    const float* b1 = (const float*)d_in[3];
    const float* W2 = (const float*)d_in[4];
    const float* b2 = (const float*)d_in[5];
    float* out = (float*)d_out;

    static cudaStream_t s_prep = nullptr;
    static cudaEvent_t ev_fork = nullptr, ev_join = nullptr;
    if (s_prep == nullptr) {
        cudaStreamCreateWithFlags(&s_prep, cudaStreamNonBlocking);
        cudaEventCreateWithFlags(&ev_fork, cudaEventDisableTiming);
        cudaEventCreateWithFlags(&ev_join, cudaEventDisableTiming);
        cudaFuncSetAttribute(k_gemm1_tc, cudaFuncAttributeMaxDynamicSharedMemorySize, G1_SMEM);
    }

    // fork: prep chain on side stream, gemm1 on main stream
    cudaEventRecord(ev_fork, 0);
    cudaStreamWaitEvent(s_prep, ev_fork, 0);

    k_init<<<(N_NODES + 255) / 256, 256, 0, s_prep>>>((const unsigned*)ei);
    k_count<<<(N_EDGES + 255) / 256, 256, 0, s_prep>>>(ei);
    k_scan1<<<SCAN_NBLK, 256, 0, s_prep>>>();
    k_scan2<<<1, 128, 0, s_prep>>>();
    k_scan3<<<(N_NODES + 255) / 256, 256, 0, s_prep>>>();
    k_scatter<<<(N_EDGES + 255) / 256, 256, 0, s_prep>>>(ei);

    k_gemm1_tc<<<(N_NODES + BM - 1) / BM, 256, G1_SMEM>>>(x, W1);

    // join
    cudaEventRecord(ev_join, s_prep);
    cudaStreamWaitEvent(0, ev_join, 0);

    k_agg1_g<<<(N_NODES * 32 + 255) / 256, 256>>>(b1);
    k_gemm2_tc<<<(N_NODES + 127) / 128, 256>>>(W2);
    k_agg2_g<<<(N_NODES * 10 + 255) / 256, 256>>>();
    k_lsm<<<(N_NODES + 3) / 4, 128>>>(b2, out);
}